// round 5
// baseline (speedup 1.0000x reference)
#include <cuda_runtime.h>
#include <cstdint>
#include <math.h>

// ---------------------------------------------------------------- constants
#define BATCH 8
#define SEQ   2048
#define CDIM  1024

#define BM 128
#define BN 128
#define BKK 32                      // fp32 elems per stage row = 128 bytes
#define NSTAGES 3
#define STAGE_BYTES (2*BM*128)      // A tile 16KB + B tile 16KB
#define SMEM_DYN (NSTAGES*STAGE_BYTES + 1024)

#define SWZ(x) ((x) ^ (((x)>>3)&0x70))

// ---------------------------------------------------------------- scratch
__device__ float g_kqv[(size_t)BATCH*SEQ*3*CDIM];  // [B*T, 3C]
__device__ float g_S  [(size_t)BATCH*SEQ*SEQ];     // [B, T, T]
__device__ float g_O  [(size_t)BATCH*SEQ*CDIM];    // [B*T, C]
__device__ float g_Wt [(size_t)3*CDIM*CDIM];       // W_kqv^T  [3C, C]
__device__ float g_WtP[(size_t)CDIM*CDIM];         // W_proj^T [C, C]
__device__ float g_Vt [(size_t)BATCH*CDIM*SEQ];    // V^T per batch [C, T]

// ---------------------------------------------------------------- ptx utils
__device__ __forceinline__ uint32_t smem_u32(const void* p){
    uint32_t a;
    asm("{ .reg .u64 t; cvta.to.shared.u64 t, %1; cvt.u32.u64 %0, t; }"
        : "=r"(a) : "l"(p));
    return a;
}
__device__ __forceinline__ void cp16(uint32_t dst, const void* src){
    asm volatile("cp.async.ca.shared.global [%0], [%1], 16;" :: "r"(dst), "l"(src));
}
#define CP_COMMIT() asm volatile("cp.async.commit_group;" ::: "memory")
#define CP_WAIT2()  asm volatile("cp.async.wait_group 2;" ::: "memory")

__device__ __forceinline__ void ldm_x4(uint32_t& r0, uint32_t& r1,
                                       uint32_t& r2, uint32_t& r3, uint32_t a){
    asm volatile("ldmatrix.sync.aligned.m8n8.x4.shared.b16 {%0,%1,%2,%3}, [%4];"
        : "=r"(r0), "=r"(r1), "=r"(r2), "=r"(r3) : "r"(a));
}
#define CVT_TF32(x) asm volatile("cvt.rna.tf32.f32 %0, %0;" : "+r"(x))

__device__ __forceinline__ float tf32r(float x){
    uint32_t u = __float_as_uint(x);
    asm("cvt.rna.tf32.f32 %0, %0;" : "+r"(u));
    return __uint_as_float(u);
}

__device__ __forceinline__ void mma_m16n8k8(float* c, const uint32_t* a,
                                            uint32_t b0, uint32_t b1){
    asm volatile(
        "mma.sync.aligned.m16n8k8.row.col.f32.tf32.tf32.f32 "
        "{%0,%1,%2,%3}, {%4,%5,%6,%7}, {%8,%9}, {%0,%1,%2,%3};"
        : "+f"(c[0]), "+f"(c[1]), "+f"(c[2]), "+f"(c[3])
        : "r"(a[0]), "r"(a[1]), "r"(a[2]), "r"(a[3]), "r"(b0), "r"(b1));
}

// ---------------------------------------------------------------- tile loader
__device__ __forceinline__ void load_tile(uint32_t sA, uint32_t sB,
    const float* __restrict__ Ab, const float* __restrict__ Bb,
    int lda, int ldb, int k0, int tid)
{
#pragma unroll
    for (int i = 0; i < 4; i++) {
        int idx = tid + i*256;
        int row = idx >> 3;
        int ck  = (idx & 7) << 2;
        uint32_t so = SWZ((uint32_t)(row*128 + ck*4));
        cp16(sA + so, Ab + (size_t)row*lda + k0 + ck);
        cp16(sB + so, Bb + (size_t)row*ldb + k0 + ck);
    }
}

// ---------------------------------------------------------------- mma GEMM
// C[bz][m][n] = alpha * sum_k A[bz][m][k] * B[bz][n][k]  (+ bias[n])
// NT gemm, tf32 tensor cores. CVTA: round A fragments (A not pre-rounded).
// ROUND: tf32-round the output (it feeds another GEMM).
template<bool CSKIP, bool CK, bool HB, bool CVTA, bool ROUND>
__global__ void __launch_bounds__(256) gemm_tc(
    const float* __restrict__ A, const float* __restrict__ B,
    float* __restrict__ C, const float* __restrict__ bias,
    int K, int lda, int ldb, int ldc, long sA, long sB, long sC, float alpha)
{
    const int bx = blockIdx.x, by = blockIdx.y, bz = blockIdx.z;
    if (CSKIP && bx > by) return;

    extern __shared__ char smem[];
    const uint32_t tb = (smem_u32(smem) + 1023) & ~1023u;
    const int tid = threadIdx.x, wid = tid >> 5, lid = tid & 31;
    const int wm = wid & 1;        // 2 m-blocks of 64
    const int wn = wid >> 1;       // 4 n-blocks of 32

    const float* Ab = A + (size_t)bz*sA + (size_t)by*BM*lda;
    const float* Bb = B + (size_t)bz*sB + (size_t)bx*BN*ldb;
    float* Cb = C + (size_t)bz*sC;
    const int kEnd = CK ? min(K, (by+1)*BM) : K;
    const int iters = kEnd >> 5;

    float acc[4][4][4];
#pragma unroll
    for (int i = 0; i < 4; i++)
#pragma unroll
        for (int j = 0; j < 4; j++)
#pragma unroll
            for (int r = 0; r < 4; r++) acc[i][j][r] = 0.0f;

    const uint32_t aRow  = (uint32_t)((wm*64 + (lid & 15)) * 128);
    const uint32_t aKoff = (uint32_t)((lid >> 4) * 16);
    const uint32_t bRow  = (uint32_t)((wn*32 + (lid & 7) + ((lid >> 4) * 8)) * 128);
    const uint32_t bKoff = (uint32_t)(((lid >> 3) & 1) * 16);

#pragma unroll
    for (int s = 0; s < NSTAGES; s++) {
        load_tile(tb + s*STAGE_BYTES, tb + s*STAGE_BYTES + 16384,
                  Ab, Bb, lda, ldb, s*BKK, tid);
        CP_COMMIT();
    }

    for (int it = 0; it < iters; ++it) {
        const int s = it % NSTAGES;
        const uint32_t sAb = tb + s*STAGE_BYTES;
        const uint32_t sBb = sAb + 16384;
        CP_WAIT2();
        __syncthreads();

#pragma unroll
        for (int kc = 0; kc < 4; kc++) {
            const uint32_t kb = (uint32_t)(kc * 32);
            uint32_t a[4][4];
#pragma unroll
            for (int i = 0; i < 4; i++) {
                uint32_t off = aRow + (uint32_t)(i*16*128) + kb + aKoff;
                ldm_x4(a[i][0], a[i][1], a[i][2], a[i][3], sAb + SWZ(off));
            }
            uint32_t b[2][4];
#pragma unroll
            for (int p = 0; p < 2; p++) {
                uint32_t off = bRow + (uint32_t)(p*16*128) + kb + bKoff;
                ldm_x4(b[p][0], b[p][1], b[p][2], b[p][3], sBb + SWZ(off));
            }
            if (CVTA) {
#pragma unroll
                for (int i = 0; i < 4; i++) {
                    CVT_TF32(a[i][0]); CVT_TF32(a[i][1]);
                    CVT_TF32(a[i][2]); CVT_TF32(a[i][3]);
                }
            }
#pragma unroll
            for (int i = 0; i < 4; i++)
#pragma unroll
                for (int j = 0; j < 4; j++)
                    mma_m16n8k8(acc[i][j], a[i],
                                b[j >> 1][(j & 1)*2], b[j >> 1][(j & 1)*2 + 1]);
        }

        __syncthreads();
        const int nit = it + NSTAGES;
        if (nit < iters)
            load_tile(tb + s*STAGE_BYTES, tb + s*STAGE_BYTES + 16384,
                      Ab, Bb, lda, ldb, nit*BKK, tid);
        CP_COMMIT();
    }

    const int rowg = by*BM + wm*64 + (lid >> 2);
    const int colg = bx*BN + wn*32 + (lid & 3)*2;
#pragma unroll
    for (int j = 0; j < 4; j++) {
        const int c = colg + j*8;
        float2 bv = make_float2(0.f, 0.f);
        if (HB) bv = *(const float2*)(bias + c);
#pragma unroll
        for (int i = 0; i < 4; i++) {
            const int r = rowg + i*16;
            float2 v0, v1;
            v0.x = acc[i][j][0]*alpha + bv.x;
            v0.y = acc[i][j][1]*alpha + bv.y;
            v1.x = acc[i][j][2]*alpha + bv.x;
            v1.y = acc[i][j][3]*alpha + bv.y;
            if (ROUND) {
                v0.x = tf32r(v0.x); v0.y = tf32r(v0.y);
                v1.x = tf32r(v1.x); v1.y = tf32r(v1.y);
            }
            *(float2*)(Cb + (size_t)r*ldc + c)     = v0;
            *(float2*)(Cb + (size_t)(r+8)*ldc + c) = v1;
        }
    }
}

// ---------------------------------------------------------------- transpose
// out[c][r] = tf32_round(in[r][c])
__global__ void __launch_bounds__(256) transpose_g(
    const float* __restrict__ in, float* __restrict__ out,
    int ldin, int ldout, long sIn, long sOut)
{
    __shared__ float t[32][33];
    const int b = blockIdx.z;
    in  += (size_t)b * sIn;
    out += (size_t)b * sOut;
    const int x = blockIdx.x * 32;
    const int y = blockIdx.y * 32;
#pragma unroll
    for (int j = threadIdx.y; j < 32; j += 8)
        t[j][threadIdx.x] = tf32r(in[(size_t)(y + j)*ldin + x + threadIdx.x]);
    __syncthreads();
#pragma unroll
    for (int j = threadIdx.y; j < 32; j += 8)
        out[(size_t)(x + j)*ldout + y + threadIdx.x] = t[threadIdx.x][j];
}

// ---------------------------------------------------------------- softmax
__global__ __launch_bounds__(256)
void softmax_causal(float* __restrict__ S, int T)
{
    const int i = blockIdx.x;
    const int b = blockIdx.y;
    float* row = S + ((size_t)b*T + i)*T;
    const int L = i + 1;
    const int tid = threadIdx.x;

    __shared__ float red[8];
    __shared__ float bval;

    float m = -1e30f;
    for (int j = tid; j < L; j += 256) m = fmaxf(m, row[j]);
#pragma unroll
    for (int o = 16; o; o >>= 1) m = fmaxf(m, __shfl_xor_sync(0xffffffffu, m, o));
    if ((tid & 31) == 0) red[tid >> 5] = m;
    __syncthreads();
    if (tid == 0) {
        float mm = red[0];
#pragma unroll
        for (int w = 1; w < 8; w++) mm = fmaxf(mm, red[w]);
        bval = mm;
    }
    __syncthreads();
    m = bval;
    __syncthreads();

    float s = 0.0f;
    for (int j = tid; j < L; j += 256) {
        float e = expf(row[j] - m);
        row[j] = e;
        s += e;
    }
#pragma unroll
    for (int o = 16; o; o >>= 1) s += __shfl_xor_sync(0xffffffffu, s, o);
    if ((tid & 31) == 0) red[tid >> 5] = s;
    __syncthreads();
    if (tid == 0) {
        float ss = 0.0f;
#pragma unroll
        for (int w = 0; w < 8; w++) ss += red[w];
        bval = ss;
    }
    __syncthreads();
    const float inv = 1.0f / bval;

    // write tf32-rounded probabilities (consumed by the PV tensor-core GEMM)
    for (int j = tid; j < L; j += 256) row[j] = tf32r(row[j] * inv);
    const int end = ((i >> 7) + 1) << 7;
    for (int j = L + tid; j < end; j += 256) row[j] = 0.0f;
}

// ---------------------------------------------------------------- launch
extern "C" void kernel_launch(void* const* d_in, const int* in_sizes, int n_in,
                              void* d_out, int out_size)
{
    (void)in_sizes; (void)n_in; (void)out_size;
    const float* x      = (const float*)d_in[0];
    const float* W_kqv  = (const float*)d_in[1];
    const float* b_kqv  = (const float*)d_in[2];
    const float* W_proj = (const float*)d_in[3];
    const float* b_proj = (const float*)d_in[4];
    float* out = (float*)d_out;

    float *kqv, *S, *O, *Wt, *WtP, *Vt;
    cudaGetSymbolAddress((void**)&kqv, g_kqv);
    cudaGetSymbolAddress((void**)&S,   g_S);
    cudaGetSymbolAddress((void**)&O,   g_O);
    cudaGetSymbolAddress((void**)&Wt,  g_Wt);
    cudaGetSymbolAddress((void**)&WtP, g_WtP);
    cudaGetSymbolAddress((void**)&Vt,  g_Vt);

    const int B = BATCH, T = SEQ, C = CDIM;
    const float scale = 1.0f / sqrtf((float)T);
    const long sBT3C = (long)T*3*C;

    cudaFuncSetAttribute(gemm_tc<false,false,true,true,true>,
        cudaFuncAttributeMaxDynamicSharedMemorySize, SMEM_DYN);
    cudaFuncSetAttribute(gemm_tc<true,false,false,false,false>,
        cudaFuncAttributeMaxDynamicSharedMemorySize, SMEM_DYN);
    cudaFuncSetAttribute(gemm_tc<false,true,false,false,true>,
        cudaFuncAttributeMaxDynamicSharedMemorySize, SMEM_DYN);
    cudaFuncSetAttribute(gemm_tc<false,false,true,false,false>,
        cudaFuncAttributeMaxDynamicSharedMemorySize, SMEM_DYN);

    // launch order chosen so ncu (-s 5 -c 1) profiles launch #6 = PV GEMM.
    // 1) Wt = W_kqv^T (tf32-rounded)
    transpose_g<<<dim3(3*C/32, C/32, 1), dim3(32,8)>>>(W_kqv, Wt, 3*C, C, 0, 0);

    // 2) kqv = x @ W_kqv + b_kqv  (A=x unrounded -> CVTA; output tf32-rounded)
    gemm_tc<false,false,true,true,true><<<dim3(3*C/BN, (B*T)/BM, 1), 256, SMEM_DYN>>>(
        x, Wt, kqv, b_kqv, C, C, C, 3*C, 0, 0, 0, 1.0f);

    // 3) Vt[b][c][t] = kqv[b*T+t][2C+c]
    transpose_g<<<dim3(C/32, T/32, B), dim3(32,8)>>>(
        kqv + 2*C, Vt, 3*C, T, sBT3C, (long)C*T);

    // 4) S = Q @ K^T * scale (causal block-skip)
    gemm_tc<true,false,false,false,false><<<dim3(T/BN, T/BM, B), 256, SMEM_DYN>>>(
        kqv + C, kqv, S, nullptr, C, 3*C, 3*C, T,
        sBT3C, sBT3C, (long)T*T, scale);

    // 5) causal softmax (writes tf32-rounded P)
    softmax_causal<<<dim3(T, B, 1), 256>>>(S, T);

    // 6) O = P @ V (causal k-limit)  <-- ncu-profiled launch
    gemm_tc<false,true,false,false,true><<<dim3(C/BN, T/BM, B), 256, SMEM_DYN>>>(
        S, Vt, O, nullptr, T, T, T, C,
        (long)T*T, (long)C*T, (long)T*C, 1.0f);

    // 7) WtP = W_proj^T
    transpose_g<<<dim3(C/32, C/32, 1), dim3(32,8)>>>(W_proj, WtP, C, C, 0, 0);

    // 8) out = O @ W_proj + b_proj
    gemm_tc<false,false,true,false,false><<<dim3(C/BN, (B*T)/BM, 1), 256, SMEM_DYN>>>(
        O, WtP, out, b_proj, C, C, C, C, 0, 0, 0, 1.0f);
}

// round 6
// speedup vs baseline: 1.0836x; 1.0836x over previous
#include <cuda_runtime.h>
#include <cstdint>
#include <math.h>

// ---------------------------------------------------------------- constants
#define BATCH 8
#define SEQ   2048
#define CDIM  1024

#define BM 128
#define BN 128
#define BKK 32                      // fp32 elems per stage row = 128 bytes
#define NSTAGES 2
#define STAGE_BYTES (2*BM*128)      // A tile 16KB + B tile 16KB
#define SMEM_DYN (NSTAGES*STAGE_BYTES + 1024)

#define SWZ(x) ((x) ^ (((x)>>3)&0x70))

// ---------------------------------------------------------------- scratch
__device__ float g_kqv[(size_t)BATCH*SEQ*3*CDIM];  // [B*T, 3C]
__device__ float g_S  [(size_t)BATCH*SEQ*SEQ];     // [B, T, T]
__device__ float g_O  [(size_t)BATCH*SEQ*CDIM];    // [B*T, C]
__device__ float g_Wt [(size_t)3*CDIM*CDIM];       // W_kqv^T  [3C, C]
__device__ float g_WtP[(size_t)CDIM*CDIM];         // W_proj^T [C, C]
__device__ float g_Vt [(size_t)BATCH*CDIM*SEQ];    // V^T per batch [C, T]

// ---------------------------------------------------------------- ptx utils
__device__ __forceinline__ uint32_t smem_u32(const void* p){
    uint32_t a;
    asm("{ .reg .u64 t; cvta.to.shared.u64 t, %1; cvt.u32.u64 %0, t; }"
        : "=r"(a) : "l"(p));
    return a;
}
__device__ __forceinline__ void cp16(uint32_t dst, const void* src){
    asm volatile("cp.async.ca.shared.global [%0], [%1], 16;" :: "r"(dst), "l"(src));
}
#define CP_COMMIT() asm volatile("cp.async.commit_group;" ::: "memory")
#define CP_WAIT1()  asm volatile("cp.async.wait_group 1;" ::: "memory")

__device__ __forceinline__ void ldm_x4(uint32_t& r0, uint32_t& r1,
                                       uint32_t& r2, uint32_t& r3, uint32_t a){
    asm volatile("ldmatrix.sync.aligned.m8n8.x4.shared.b16 {%0,%1,%2,%3}, [%4];"
        : "=r"(r0), "=r"(r1), "=r"(r2), "=r"(r3) : "r"(a));
}
#define CVT_TF32(x) asm volatile("cvt.rna.tf32.f32 %0, %0;" : "+r"(x))

__device__ __forceinline__ float tf32r(float x){
    uint32_t u = __float_as_uint(x);
    asm("cvt.rna.tf32.f32 %0, %0;" : "+r"(u));
    return __uint_as_float(u);
}

__device__ __forceinline__ void mma_m16n8k8(float* c, const uint32_t* a,
                                            uint32_t b0, uint32_t b1){
    asm volatile(
        "mma.sync.aligned.m16n8k8.row.col.f32.tf32.tf32.f32 "
        "{%0,%1,%2,%3}, {%4,%5,%6,%7}, {%8,%9}, {%0,%1,%2,%3};"
        : "+f"(c[0]), "+f"(c[1]), "+f"(c[2]), "+f"(c[3])
        : "r"(a[0]), "r"(a[1]), "r"(a[2]), "r"(a[3]), "r"(b0), "r"(b1));
}

// ---------------------------------------------------------------- tile loader
__device__ __forceinline__ void load_tile(uint32_t sA, uint32_t sB,
    const float* __restrict__ Ab, const float* __restrict__ Bb,
    int lda, int ldb, int k0, int tid)
{
#pragma unroll
    for (int i = 0; i < 4; i++) {
        int idx = tid + i*256;
        int row = idx >> 3;
        int ck  = (idx & 7) << 2;
        uint32_t so = SWZ((uint32_t)(row*128 + ck*4));
        cp16(sA + so, Ab + (size_t)row*lda + k0 + ck);
        cp16(sB + so, Bb + (size_t)row*ldb + k0 + ck);
    }
}

// ---------------------------------------------------------------- mma GEMM
// C[bz][m][n] = alpha * sum_k A[bz][m][k] * B[bz][n][k]  (+ bias[n])
// NT gemm, tf32 tensor cores. CVTA: round A fragments (A not pre-rounded).
// ROUND: tf32-round the output (it feeds another GEMM).
template<bool CSKIP, bool CK, bool HB, bool CVTA, bool ROUND>
__global__ void __launch_bounds__(256, 2) gemm_tc(
    const float* __restrict__ A, const float* __restrict__ B,
    float* __restrict__ C, const float* __restrict__ bias,
    int K, int lda, int ldb, int ldc, long sA, long sB, long sC, float alpha)
{
    const int bx = blockIdx.x, by = blockIdx.y, bz = blockIdx.z;
    if (CSKIP && bx > by) return;

    extern __shared__ char smem[];
    const uint32_t tb = (smem_u32(smem) + 1023) & ~1023u;
    const int tid = threadIdx.x, wid = tid >> 5, lid = tid & 31;
    const int wm = wid & 1;        // 2 m-blocks of 64
    const int wn = wid >> 1;       // 4 n-blocks of 32

    const float* Ab = A + (size_t)bz*sA + (size_t)by*BM*lda;
    const float* Bb = B + (size_t)bz*sB + (size_t)bx*BN*ldb;
    float* Cb = C + (size_t)bz*sC;
    const int kEnd = CK ? min(K, (by+1)*BM) : K;
    const int iters = kEnd >> 5;

    float acc[4][4][4];
#pragma unroll
    for (int i = 0; i < 4; i++)
#pragma unroll
        for (int j = 0; j < 4; j++)
#pragma unroll
            for (int r = 0; r < 4; r++) acc[i][j][r] = 0.0f;

    const uint32_t aRow  = (uint32_t)((wm*64 + (lid & 15)) * 128);
    const uint32_t aKoff = (uint32_t)((lid >> 4) * 16);
    const uint32_t bRow  = (uint32_t)((wn*32 + (lid & 7) + ((lid >> 4) * 8)) * 128);
    const uint32_t bKoff = (uint32_t)(((lid >> 3) & 1) * 16);

#pragma unroll
    for (int s = 0; s < NSTAGES; s++) {
        load_tile(tb + s*STAGE_BYTES, tb + s*STAGE_BYTES + 16384,
                  Ab, Bb, lda, ldb, s*BKK, tid);
        CP_COMMIT();
    }

    for (int it = 0; it < iters; ++it) {
        const int s = it & 1;
        const uint32_t sAb = tb + s*STAGE_BYTES;
        const uint32_t sBb = sAb + 16384;
        CP_WAIT1();
        __syncthreads();

#pragma unroll
        for (int kc = 0; kc < 4; kc++) {
            const uint32_t kb = (uint32_t)(kc * 32);
            uint32_t a[4][4];
#pragma unroll
            for (int i = 0; i < 4; i++) {
                uint32_t off = aRow + (uint32_t)(i*16*128) + kb + aKoff;
                ldm_x4(a[i][0], a[i][1], a[i][2], a[i][3], sAb + SWZ(off));
            }
            uint32_t b[2][4];
#pragma unroll
            for (int p = 0; p < 2; p++) {
                uint32_t off = bRow + (uint32_t)(p*16*128) + kb + bKoff;
                ldm_x4(b[p][0], b[p][1], b[p][2], b[p][3], sBb + SWZ(off));
            }
            if (CVTA) {
#pragma unroll
                for (int i = 0; i < 4; i++) {
                    CVT_TF32(a[i][0]); CVT_TF32(a[i][1]);
                    CVT_TF32(a[i][2]); CVT_TF32(a[i][3]);
                }
            }
#pragma unroll
            for (int i = 0; i < 4; i++)
#pragma unroll
                for (int j = 0; j < 4; j++)
                    mma_m16n8k8(acc[i][j], a[i],
                                b[j >> 1][(j & 1)*2], b[j >> 1][(j & 1)*2 + 1]);
        }

        __syncthreads();
        const int nit = it + NSTAGES;
        if (nit < iters)
            load_tile(tb + s*STAGE_BYTES, tb + s*STAGE_BYTES + 16384,
                      Ab, Bb, lda, ldb, nit*BKK, tid);
        CP_COMMIT();
    }

    const int rowg = by*BM + wm*64 + (lid >> 2);
    const int colg = bx*BN + wn*32 + (lid & 3)*2;
#pragma unroll
    for (int j = 0; j < 4; j++) {
        const int c = colg + j*8;
        float2 bv = make_float2(0.f, 0.f);
        if (HB) bv = *(const float2*)(bias + c);
#pragma unroll
        for (int i = 0; i < 4; i++) {
            const int r = rowg + i*16;
            float2 v0, v1;
            v0.x = acc[i][j][0]*alpha + bv.x;
            v0.y = acc[i][j][1]*alpha + bv.y;
            v1.x = acc[i][j][2]*alpha + bv.x;
            v1.y = acc[i][j][3]*alpha + bv.y;
            if (ROUND) {
                v0.x = tf32r(v0.x); v0.y = tf32r(v0.y);
                v1.x = tf32r(v1.x); v1.y = tf32r(v1.y);
            }
            *(float2*)(Cb + (size_t)r*ldc + c)     = v0;
            *(float2*)(Cb + (size_t)(r+8)*ldc + c) = v1;
        }
    }
}

// ---------------------------------------------------------------- transpose
// out[c][r] = tf32_round(in[r][c])
__global__ void __launch_bounds__(256) transpose_g(
    const float* __restrict__ in, float* __restrict__ out,
    int ldin, int ldout, long sIn, long sOut)
{
    __shared__ float t[32][33];
    const int b = blockIdx.z;
    in  += (size_t)b * sIn;
    out += (size_t)b * sOut;
    const int x = blockIdx.x * 32;
    const int y = blockIdx.y * 32;
#pragma unroll
    for (int j = threadIdx.y; j < 32; j += 8)
        t[j][threadIdx.x] = tf32r(in[(size_t)(y + j)*ldin + x + threadIdx.x]);
    __syncthreads();
#pragma unroll
    for (int j = threadIdx.y; j < 32; j += 8)
        out[(size_t)(x + j)*ldout + y + threadIdx.x] = t[threadIdx.x][j];
}

// ---------------------------------------------------------------- softmax
__global__ __launch_bounds__(256)
void softmax_causal(float* __restrict__ S, int T)
{
    const int i = blockIdx.x;
    const int b = blockIdx.y;
    float* row = S + ((size_t)b*T + i)*T;
    const int L = i + 1;
    const int tid = threadIdx.x;

    __shared__ float red[8];
    __shared__ float bval;

    float m = -1e30f;
    for (int j = tid; j < L; j += 256) m = fmaxf(m, row[j]);
#pragma unroll
    for (int o = 16; o; o >>= 1) m = fmaxf(m, __shfl_xor_sync(0xffffffffu, m, o));
    if ((tid & 31) == 0) red[tid >> 5] = m;
    __syncthreads();
    if (tid == 0) {
        float mm = red[0];
#pragma unroll
        for (int w = 1; w < 8; w++) mm = fmaxf(mm, red[w]);
        bval = mm;
    }
    __syncthreads();
    m = bval;
    __syncthreads();

    float s = 0.0f;
    for (int j = tid; j < L; j += 256) {
        float e = expf(row[j] - m);
        row[j] = e;
        s += e;
    }
#pragma unroll
    for (int o = 16; o; o >>= 1) s += __shfl_xor_sync(0xffffffffu, s, o);
    if ((tid & 31) == 0) red[tid >> 5] = s;
    __syncthreads();
    if (tid == 0) {
        float ss = 0.0f;
#pragma unroll
        for (int w = 0; w < 8; w++) ss += red[w];
        bval = ss;
    }
    __syncthreads();
    const float inv = 1.0f / bval;

    for (int j = tid; j < L; j += 256) row[j] = tf32r(row[j] * inv);
    const int end = ((i >> 7) + 1) << 7;
    for (int j = L + tid; j < end; j += 256) row[j] = 0.0f;
}

// ---------------------------------------------------------------- launch
extern "C" void kernel_launch(void* const* d_in, const int* in_sizes, int n_in,
                              void* d_out, int out_size)
{
    (void)in_sizes; (void)n_in; (void)out_size;
    const float* x      = (const float*)d_in[0];
    const float* W_kqv  = (const float*)d_in[1];
    const float* b_kqv  = (const float*)d_in[2];
    const float* W_proj = (const float*)d_in[3];
    const float* b_proj = (const float*)d_in[4];
    float* out = (float*)d_out;

    float *kqv, *S, *O, *Wt, *WtP, *Vt;
    cudaGetSymbolAddress((void**)&kqv, g_kqv);
    cudaGetSymbolAddress((void**)&S,   g_S);
    cudaGetSymbolAddress((void**)&O,   g_O);
    cudaGetSymbolAddress((void**)&Wt,  g_Wt);
    cudaGetSymbolAddress((void**)&WtP, g_WtP);
    cudaGetSymbolAddress((void**)&Vt,  g_Vt);

    const int B = BATCH, T = SEQ, C = CDIM;
    const float scale = 1.0f / sqrtf((float)T);
    const long sBT3C = (long)T*3*C;

    cudaFuncSetAttribute(gemm_tc<false,false,true,true,true>,
        cudaFuncAttributeMaxDynamicSharedMemorySize, SMEM_DYN);
    cudaFuncSetAttribute(gemm_tc<true,false,false,false,false>,
        cudaFuncAttributeMaxDynamicSharedMemorySize, SMEM_DYN);
    cudaFuncSetAttribute(gemm_tc<false,true,false,false,true>,
        cudaFuncAttributeMaxDynamicSharedMemorySize, SMEM_DYN);
    cudaFuncSetAttribute(gemm_tc<false,false,true,false,false>,
        cudaFuncAttributeMaxDynamicSharedMemorySize, SMEM_DYN);

    // 1) Wt = W_kqv^T (tf32-rounded)
    transpose_g<<<dim3(3*C/32, C/32, 1), dim3(32,8)>>>(W_kqv, Wt, 3*C, C, 0, 0);

    // 2) kqv = x @ W_kqv + b_kqv
    gemm_tc<false,false,true,true,true><<<dim3(3*C/BN, (B*T)/BM, 1), 256, SMEM_DYN>>>(
        x, Wt, kqv, b_kqv, C, C, C, 3*C, 0, 0, 0, 1.0f);

    // 3) Vt[b][c][t] = kqv[b*T+t][2C+c]
    transpose_g<<<dim3(C/32, T/32, B), dim3(32,8)>>>(
        kqv + 2*C, Vt, 3*C, T, sBT3C, (long)C*T);

    // 4) S = Q @ K^T * scale (causal block-skip)
    gemm_tc<true,false,false,false,false><<<dim3(T/BN, T/BM, B), 256, SMEM_DYN>>>(
        kqv + C, kqv, S, nullptr, C, 3*C, 3*C, T,
        sBT3C, sBT3C, (long)T*T, scale);

    // 5) causal softmax (writes tf32-rounded P)
    softmax_causal<<<dim3(T, B, 1), 256>>>(S, T);

    // 6) O = P @ V (causal k-limit)
    gemm_tc<false,true,false,false,true><<<dim3(C/BN, T/BM, B), 256, SMEM_DYN>>>(
        S, Vt, O, nullptr, T, T, T, C,
        (long)T*T, (long)C*T, (long)T*C, 1.0f);

    // 7) WtP = W_proj^T
    transpose_g<<<dim3(C/32, C/32, 1), dim3(32,8)>>>(W_proj, WtP, C, C, 0, 0);

    // 8) out = O @ W_proj + b_proj
    gemm_tc<false,false,true,false,false><<<dim3(C/BN, (B*T)/BM, 1), 256, SMEM_DYN>>>(
        O, WtP, out, b_proj, C, C, C, C, 0, 0, 0, 1.0f);
}